// round 12
// baseline (speedup 1.0000x reference)
#include <cuda_runtime.h>
#include <cstdint>

#define UNITS        32768
#define PACKED_WORDS 1024                 // uint32 words per weight row
#define PACKED_VEC   (PACKED_WORDS / 4)   // 256 uint4 per row
#define OUT_WORDS    (UNITS / 32)         // 1024 packed output words
#define WARPS_PER_BLOCK 32
#define THREADS (WARPS_PER_BLOCK * 32)
#define WORDS_PER_BLOCK 4                 // each block produces 4 output words

__global__ __launch_bounds__(THREADS, 2)
void bitdense_kernel(const uint32_t* __restrict__ inp,
                     const uint4*    __restrict__ w,
                     const int*      __restrict__ b,
                     float*          __restrict__ out)
{
    __shared__ uint4 s_in[PACKED_VEC];   // 4 KB input stage (once per block)
    __shared__ int   s_sign[WORDS_PER_BLOCK][WARPS_PER_BLOCK];

    const int tid  = threadIdx.x;
    const int warp = tid >> 5;
    const int lane = tid & 31;

    if (tid < PACKED_VEC) {
        s_in[tid] = ((const uint4*)inp)[tid];
    }
    __syncthreads();

    // 4 sequential rows per warp; NO mid-kernel __syncthreads: each warp
    // writes a private s_sign slot, so warps stream their 16 KB of weights
    // completely independently (next row's loads overlap the REDUX drain).
    #pragma unroll
    for (int word = 0; word < WORDS_PER_BLOCK; word++) {
        const int oidx = blockIdx.x * WORDS_PER_BLOCK + word;
        const int unit = oidx * WARPS_PER_BLOCK + warp;
        const uint4* row = w + (size_t)unit * PACKED_VEC;

        int acc = 0;
        #pragma unroll
        for (int i = 0; i < 8; i++) {
            // 8 independent LDG.128, contiguous 4 KB per warp-row.
            uint4 wv = row[lane + i * 32];
            uint4 iv = s_in[lane + i * 32];
            acc += __popc(wv.x ^ iv.x) + __popc(wv.y ^ iv.y)
                 + __popc(wv.z ^ iv.z) + __popc(wv.w ^ iv.w);
        }

        int ones = __reduce_add_sync(0xffffffffu, acc);   // REDUX.SUM
        if (lane == 0) {
            int o = 32768 - 2 * ones + b[unit];
            s_sign[word][warp] = (o < 0) ? 1 : 0;
        }
    }
    __syncthreads();   // single terminal sync

    // Parallel epilogue: warp k packs output word k.
    // packbits layout: unit u lands at word-bit (u ^ 7) (MSB-first per byte,
    // bytes little-endian); XOR-7 is self-inverse -> lane i votes the sign
    // of unit (i ^ 7) and ballot emits the word directly.
    if (warp < WORDS_PER_BLOCK) {
        unsigned wrd = __ballot_sync(0xffffffffu, s_sign[warp][lane ^ 7]);
        if (lane == 0) {
            // Expected = packed word viewed as SIGNED int32, compared by
            // value against our float32 output buffer.
            out[blockIdx.x * WORDS_PER_BLOCK + warp] = (float)(int32_t)wrd;
        }
    }
}

// Zero any tail of d_out beyond OUT_WORDS (defensive).
__global__ void tail_zero_kernel(float* __restrict__ out, int begin, int n)
{
    int i = begin + blockIdx.x * blockDim.x + threadIdx.x;
    if (i < n) out[i] = 0.0f;
}

extern "C" void kernel_launch(void* const* d_in, const int* in_sizes, int n_in,
                              void* d_out, int out_size)
{
    // Bind inputs by relative size (robust to metadata ordering):
    // largest buffer = w, smallest = inputs, remaining = b.
    int iw = 0, ii = 0;
    for (int i = 1; i < n_in; i++) {
        if (in_sizes[i] > in_sizes[iw]) iw = i;
        if (in_sizes[i] < in_sizes[ii]) ii = i;
    }
    int ib = 0;
    for (int i = 0; i < n_in; i++) if (i != iw && i != ii) { ib = i; break; }

    const uint32_t* inp = (const uint32_t*)d_in[ii];  // [1024] packed input bits
    const uint4*    w   = (const uint4*)   d_in[iw];  // [32768,1024] packed weights
    const int*      b   = (const int*)     d_in[ib];  // [32768] bias
    float*          out = (float*)         d_out;     // [1024] packed words (signed value)

    // 256 CTAs x 1024 thr at occ 2 -> 296 resident slots: single wave.
    dim3 grid(OUT_WORDS / WORDS_PER_BLOCK);
    dim3 block(THREADS);
    bitdense_kernel<<<grid, block>>>(inp, w, b, out);

    if (out_size > OUT_WORDS) {
        int tail = out_size - OUT_WORDS;
        tail_zero_kernel<<<(tail + 255) / 256, 256>>>(out, OUT_WORDS, out_size);
    }
}

// round 13
// speedup vs baseline: 1.2477x; 1.2477x over previous
#include <cuda_runtime.h>
#include <cstdint>

#define UNITS        32768
#define PACKED_WORDS 1024                 // uint32 words per weight row
#define PACKED_VEC   (PACKED_WORDS / 4)   // 256 uint4 per row
#define OUT_WORDS    (UNITS / 32)         // 1024 packed output words
#define WARPS_PER_BLOCK 32
#define THREADS (WARPS_PER_BLOCK * 32)
#define WORDS_PER_BLOCK 2                 // each block produces 2 output words

__global__ __launch_bounds__(THREADS, 2)
void bitdense_kernel(const uint32_t* __restrict__ inp,
                     const uint4*    __restrict__ w,
                     const int*      __restrict__ b,
                     float*          __restrict__ out)
{
    __shared__ uint4 s_in[PACKED_VEC];   // 4 KB input stage (once per block)
    __shared__ int   s_sign[WORDS_PER_BLOCK][WARPS_PER_BLOCK];

    const int tid  = threadIdx.x;
    const int warp = tid >> 5;
    const int lane = tid & 31;

    if (tid < PACKED_VEC) {
        s_in[tid] = ((const uint4*)inp)[tid];
    }
    __syncthreads();

    // 2 sequential rows per warp with NO block-wide sync between them:
    // each warp writes a private s_sign slot, so the second row's loads
    // issue while the first row's REDUX drains. Grid 512 (~3.5 CTAs/SM)
    // keeps CTA-level load-balance fine-grained (R12's grid-256 lesson).
    #pragma unroll
    for (int word = 0; word < WORDS_PER_BLOCK; word++) {
        const int oidx = blockIdx.x * WORDS_PER_BLOCK + word;
        const int unit = oidx * WARPS_PER_BLOCK + warp;
        const uint4* row = w + (size_t)unit * PACKED_VEC;

        int acc = 0;
        #pragma unroll
        for (int i = 0; i < 8; i++) {
            // 8 independent LDG.128, contiguous 4 KB per warp-row.
            uint4 wv = row[lane + i * 32];
            uint4 iv = s_in[lane + i * 32];
            acc += __popc(wv.x ^ iv.x) + __popc(wv.y ^ iv.y)
                 + __popc(wv.z ^ iv.z) + __popc(wv.w ^ iv.w);
        }

        int ones = __reduce_add_sync(0xffffffffu, acc);   // REDUX.SUM
        if (lane == 0) {
            int o = 32768 - 2 * ones + b[unit];
            s_sign[word][warp] = (o < 0) ? 1 : 0;
        }
    }
    __syncthreads();   // single terminal sync

    // Parallel epilogue: warp k packs output word k.
    // packbits layout: unit u lands at word-bit (u ^ 7) (MSB-first per byte,
    // bytes little-endian); XOR-7 is self-inverse -> lane i votes the sign
    // of unit (i ^ 7) and ballot emits the word directly.
    if (warp < WORDS_PER_BLOCK) {
        unsigned wrd = __ballot_sync(0xffffffffu, s_sign[warp][lane ^ 7]);
        if (lane == 0) {
            // Expected = packed word viewed as SIGNED int32, compared by
            // value against our float32 output buffer.
            out[blockIdx.x * WORDS_PER_BLOCK + warp] = (float)(int32_t)wrd;
        }
    }
}

// Zero any tail of d_out beyond OUT_WORDS (defensive).
__global__ void tail_zero_kernel(float* __restrict__ out, int begin, int n)
{
    int i = begin + blockIdx.x * blockDim.x + threadIdx.x;
    if (i < n) out[i] = 0.0f;
}

extern "C" void kernel_launch(void* const* d_in, const int* in_sizes, int n_in,
                              void* d_out, int out_size)
{
    // Bind inputs by relative size (robust to metadata ordering):
    // largest buffer = w, smallest = inputs, remaining = b.
    int iw = 0, ii = 0;
    for (int i = 1; i < n_in; i++) {
        if (in_sizes[i] > in_sizes[iw]) iw = i;
        if (in_sizes[i] < in_sizes[ii]) ii = i;
    }
    int ib = 0;
    for (int i = 0; i < n_in; i++) if (i != iw && i != ii) { ib = i; break; }

    const uint32_t* inp = (const uint32_t*)d_in[ii];  // [1024] packed input bits
    const uint4*    w   = (const uint4*)   d_in[iw];  // [32768,1024] packed weights
    const int*      b   = (const int*)     d_in[ib];  // [32768] bias
    float*          out = (float*)         d_out;     // [1024] packed words (signed value)

    dim3 grid(OUT_WORDS / WORDS_PER_BLOCK);  // 512 blocks x 2 output words
    dim3 block(THREADS);                     // 32 warps, one unit each per word
    bitdense_kernel<<<grid, block>>>(inp, w, b, out);

    if (out_size > OUT_WORDS) {
        int tail = out_size - OUT_WORDS;
        tail_zero_kernel<<<(tail + 255) / 256, 256>>>(out, OUT_WORDS, out_size);
    }
}

// round 14
// speedup vs baseline: 1.2594x; 1.0094x over previous
#include <cuda_runtime.h>
#include <cstdint>

#define UNITS        32768
#define PACKED_WORDS 1024                 // uint32 words per weight row
#define PACKED_VEC   (PACKED_WORDS / 4)   // 256 uint4 per row
#define OUT_WORDS    (UNITS / 32)         // 1024 packed output words
#define WARPS_PER_BLOCK 32
#define THREADS (WARPS_PER_BLOCK * 32)
#define WORDS_PER_BLOCK 2                 // each block produces 2 output words

__global__ __launch_bounds__(THREADS, 2)
void bitdense_kernel(const uint32_t* __restrict__ inp,
                     const uint4*    __restrict__ w,
                     const int*      __restrict__ b,
                     float*          __restrict__ out)
{
    __shared__ uint4 s_in[PACKED_VEC];   // 4 KB input stage (once per block)
    __shared__ int   s_sign[WORDS_PER_BLOCK][WARPS_PER_BLOCK];

    const int tid  = threadIdx.x;
    const int warp = tid >> 5;
    const int lane = tid & 31;

    if (tid < PACKED_VEC) {
        s_in[tid] = ((const uint4*)inp)[tid];
    }
    __syncthreads();

    // LOCKSTEP streaming (measured winner, R8 vs R13): exactly one
    // __syncthreads per word keeps all 32 warps issuing loads into the same
    // contiguous 128 KB window -> dense DRAM page hits. Private s_sign slots
    // per word remove R8's second sync and its serialized mid-epilogue.
    #pragma unroll
    for (int word = 0; word < WORDS_PER_BLOCK; word++) {
        const int oidx = blockIdx.x * WORDS_PER_BLOCK + word;
        const int unit = oidx * WARPS_PER_BLOCK + warp;   // one warp per row
        const uint4* row = w + (size_t)unit * PACKED_VEC;

        int acc = 0;
        #pragma unroll
        for (int i = 0; i < 8; i++) {
            // 8 independent LDG.128, contiguous 4 KB per warp-row.
            uint4 wv = row[lane + i * 32];
            uint4 iv = s_in[lane + i * 32];
            acc += __popc(wv.x ^ iv.x) + __popc(wv.y ^ iv.y)
                 + __popc(wv.z ^ iv.z) + __popc(wv.w ^ iv.w);
        }

        int ones = __reduce_add_sync(0xffffffffu, acc);   // REDUX.SUM
        if (lane == 0) {
            int o = 32768 - 2 * ones + b[unit];
            s_sign[word][warp] = (o < 0) ? 1 : 0;
        }
        __syncthreads();   // one lockstep sync per word
    }

    // Parallel epilogue: warp k packs output word k.
    // packbits layout: unit u lands at word-bit (u ^ 7) (MSB-first per byte,
    // bytes little-endian); XOR-7 is self-inverse -> lane i votes the sign
    // of unit (i ^ 7) and ballot emits the word directly.
    if (warp < WORDS_PER_BLOCK) {
        unsigned wrd = __ballot_sync(0xffffffffu, s_sign[warp][lane ^ 7]);
        if (lane == 0) {
            // Expected = packed word viewed as SIGNED int32, compared by
            // value against our float32 output buffer.
            out[blockIdx.x * WORDS_PER_BLOCK + warp] = (float)(int32_t)wrd;
        }
    }
}

// Zero any tail of d_out beyond OUT_WORDS (defensive).
__global__ void tail_zero_kernel(float* __restrict__ out, int begin, int n)
{
    int i = begin + blockIdx.x * blockDim.x + threadIdx.x;
    if (i < n) out[i] = 0.0f;
}

extern "C" void kernel_launch(void* const* d_in, const int* in_sizes, int n_in,
                              void* d_out, int out_size)
{
    // Bind inputs by relative size (robust to metadata ordering):
    // largest buffer = w, smallest = inputs, remaining = b.
    int iw = 0, ii = 0;
    for (int i = 1; i < n_in; i++) {
        if (in_sizes[i] > in_sizes[iw]) iw = i;
        if (in_sizes[i] < in_sizes[ii]) ii = i;
    }
    int ib = 0;
    for (int i = 0; i < n_in; i++) if (i != iw && i != ii) { ib = i; break; }

    const uint32_t* inp = (const uint32_t*)d_in[ii];  // [1024] packed input bits
    const uint4*    w   = (const uint4*)   d_in[iw];  // [32768,1024] packed weights
    const int*      b   = (const int*)     d_in[ib];  // [32768] bias
    float*          out = (float*)         d_out;     // [1024] packed words (signed value)

    dim3 grid(OUT_WORDS / WORDS_PER_BLOCK);  // 512 blocks x 2 output words
    dim3 block(THREADS);                     // 32 warps, one unit each per word
    bitdense_kernel<<<grid, block>>>(inp, w, b, out);

    if (out_size > OUT_WORDS) {
        int tail = out_size - OUT_WORDS;
        tail_zero_kernel<<<(tail + 255) / 256, 256>>>(out, OUT_WORDS, out_size);
    }
}

// round 15
// speedup vs baseline: 1.3640x; 1.0830x over previous
#include <cuda_runtime.h>
#include <cstdint>

// FINAL: R8 configuration — empirical argmax over 9 measured variants.
// 512 CTAs x 1024 threads (occ 2), warp-per-row, 2 output words per CTA,
// lockstep __syncthreads per word (phase-aligns all 64 warps/SM into one
// contiguous 128KB DRAM window), REDUX.SUM warp reduce, ballot epilogue
// with the packbits (u^7) bit permutation folded into the lane mapping.

#define UNITS        32768
#define PACKED_WORDS 1024                 // uint32 words per weight row
#define PACKED_VEC   (PACKED_WORDS / 4)   // 256 uint4 per row
#define OUT_WORDS    (UNITS / 32)         // 1024 packed output words
#define WARPS_PER_BLOCK 32
#define THREADS (WARPS_PER_BLOCK * 32)
#define WORDS_PER_BLOCK 2                 // each block produces 2 output words

__global__ __launch_bounds__(THREADS, 2)
void bitdense_kernel(const uint32_t* __restrict__ inp,
                     const uint4*    __restrict__ w,
                     const int*      __restrict__ b,
                     float*          __restrict__ out)
{
    __shared__ uint4 s_in[PACKED_VEC];   // 4 KB input stage (once per block)
    __shared__ int   s_sign[WARPS_PER_BLOCK];

    const int tid  = threadIdx.x;
    const int warp = tid >> 5;
    const int lane = tid & 31;

    if (tid < PACKED_VEC) {
        s_in[tid] = ((const uint4*)inp)[tid];
    }
    __syncthreads();

    #pragma unroll
    for (int word = 0; word < WORDS_PER_BLOCK; word++) {
        const int oidx = blockIdx.x * WORDS_PER_BLOCK + word;
        // One warp per unit (weight row).
        const int unit = oidx * WARPS_PER_BLOCK + warp;
        const uint4* row = w + (size_t)unit * PACKED_VEC;

        int acc = 0;
        #pragma unroll
        for (int i = 0; i < 8; i++) {
            // 8 independent LDG.128 per lane -> fully coalesced 512B/instr
            uint4 wv = row[lane + i * 32];
            uint4 iv = s_in[lane + i * 32];
            acc += __popc(wv.x ^ iv.x) + __popc(wv.y ^ iv.y)
                 + __popc(wv.z ^ iv.z) + __popc(wv.w ^ iv.w);
        }

        // Single-instruction warp sum (REDUX.SUM)
        int ones = __reduce_add_sync(0xffffffffu, acc);

        if (lane == 0) {
            int o = 32768 - 2 * ones + b[unit];
            s_sign[warp] = (o < 0) ? 1 : 0;
        }
        __syncthreads();

        // Pack 32 signs: unit u lands at word-bit (u ^ 7) (packbits MSB-first
        // per byte, bytes little-endian). XOR-7 is self-inverse -> lane i
        // votes the sign of unit (i ^ 7); ballot emits the word directly.
        if (warp == 0) {
            unsigned wrd = __ballot_sync(0xffffffffu, s_sign[lane ^ 7]);
            if (lane == 0) {
                // Expected = packed word viewed as SIGNED int32, compared by
                // value against our float32 output buffer.
                out[oidx] = (float)(int32_t)wrd;
            }
        }
        if (word + 1 < WORDS_PER_BLOCK) __syncthreads();
    }
}

// Zero any tail of d_out beyond OUT_WORDS (defensive).
__global__ void tail_zero_kernel(float* __restrict__ out, int begin, int n)
{
    int i = begin + blockIdx.x * blockDim.x + threadIdx.x;
    if (i < n) out[i] = 0.0f;
}

extern "C" void kernel_launch(void* const* d_in, const int* in_sizes, int n_in,
                              void* d_out, int out_size)
{
    // Bind inputs by relative size (robust to metadata ordering):
    // largest buffer = w, smallest = inputs, remaining = b.
    int iw = 0, ii = 0;
    for (int i = 1; i < n_in; i++) {
        if (in_sizes[i] > in_sizes[iw]) iw = i;
        if (in_sizes[i] < in_sizes[ii]) ii = i;
    }
    int ib = 0;
    for (int i = 0; i < n_in; i++) if (i != iw && i != ii) { ib = i; break; }

    const uint32_t* inp = (const uint32_t*)d_in[ii];  // [1024] packed input bits
    const uint4*    w   = (const uint4*)   d_in[iw];  // [32768,1024] packed weights
    const int*      b   = (const int*)     d_in[ib];  // [32768] bias
    float*          out = (float*)         d_out;     // [1024] packed words (signed value)

    dim3 grid(OUT_WORDS / WORDS_PER_BLOCK);  // 512 blocks x 2 output words
    dim3 block(THREADS);                     // 32 warps, one unit each per word
    bitdense_kernel<<<grid, block>>>(inp, w, b, out);

    if (out_size > OUT_WORDS) {
        int tail = out_size - OUT_WORDS;
        tail_zero_kernel<<<(tail + 255) / 256, 256>>>(out, OUT_WORDS, out_size);
    }
}